// round 17
// baseline (speedup 1.0000x reference)
#include <cuda_runtime.h>
#include <cuda_fp16.h>
#include <cstdint>

// ---------------- problem constants ----------------
#define HW_      65536
#define CDIM     64
#define NKP      400
#define KP_HALF  200        // kp per CTA (2 halves)
#define KP_PAD   208        // 13 frags x 16
#define NFRAG    13
#define PMAX     2
#define NSTRIP   74         // x 2 halves x P=2 -> 296 CTAs = 2 per SM
#define NCHUNK_G 1024       // 65536 / 64
#define CHUNK_M  64
#define NTHREADS 256        // 8 warps
#define LOGIT_C  144.26950408889634f   // 100 * log2(e)

// smem: A rows 144B stride (128B fp16 data + 16B pad); B bufs 64 rows x 144B
#define SA     0
#define SB     29952        // KP_PAD*144
#define SMEMSZ 48384        // SB + 2*9216

// ---------------- device scratch ----------------
__device__ float4 g_part4[PMAX * NKP * NSTRIP]; // (S, X, Y, _) per kp per strip

// ---------------- helpers ----------------
__device__ __forceinline__ float ex2f(float x) {
    float y; asm("ex2.approx.ftz.f32 %0, %1;" : "=f"(y) : "f"(x)); return y;
}
__device__ __forceinline__ uint32_t pkh2(float a, float b) {
    __half2 h = __floats2half2_rn(a, b);
    return *reinterpret_cast<uint32_t*>(&h);
}
__device__ __forceinline__ void ldsm4(uint32_t& r0, uint32_t& r1, uint32_t& r2, uint32_t& r3,
                                      uint32_t addr) {
    asm volatile("ldmatrix.sync.aligned.m8n8.x4.shared.b16 {%0,%1,%2,%3}, [%4];"
                 : "=r"(r0), "=r"(r1), "=r"(r2), "=r"(r3) : "r"(addr));
}
__device__ __forceinline__ void mma16816(float* c, const uint32_t* a, uint32_t b0, uint32_t b1) {
    asm volatile(
        "mma.sync.aligned.m16n8k16.row.col.f32.f16.f16.f32 "
        "{%0,%1,%2,%3}, {%4,%5,%6,%7}, {%8,%9}, {%0,%1,%2,%3};"
        : "+f"(c[0]), "+f"(c[1]), "+f"(c[2]), "+f"(c[3])
        : "r"(a[0]), "r"(a[1]), "r"(a[2]), "r"(a[3]), "r"(b0), "r"(b1));
}

// ---------------- kernel 1: fp16 mma GEMM + fused softmax moments ----------------
// grid (NSTRIP, 2 kp-halves, P), 256 threads / 8 warps, 2 CTAs per SM.
// CTA owns 200 keypoints (13 frags of 16, last half-padded): warp w owns frag w;
// warps 0-4 also own frag w+8 (processed SEQUENTIALLY, c[] reused -> low regs).
// Staging: all 8 warps; thread owns column m = w*8+(lane&7), k-quarter kg = lane>>3;
// column norms via intra-warp shfl. One __syncthreads per 64-col chunk.
__global__ void __launch_bounds__(NTHREADS, 2)
k_match(const float* __restrict__ dense, const float* __restrict__ kdesc,
        const int* __restrict__ tgt_ids, const int* __restrict__ src_ids) {
    extern __shared__ char sm[];
    const uint32_t sb = (uint32_t)__cvta_generic_to_shared(sm);
    const int tid = threadIdx.x, w = tid >> 5, lane = tid & 31;
    const int strip = blockIdx.x, kphalf = blockIdx.y, p = blockIdx.z;
    const int c0i = (strip * NCHUNK_G) / NSTRIP;
    const int c1i = ((strip + 1) * NCHUNK_G) / NSTRIP;
    const float* srcb = dense + (size_t)src_ids[p] * CDIM * HW_;

    const int mcol = w * 8 + (lane & 7);   // column within chunk (8 warps x 8 = 64)
    const int kg   = lane >> 3;            // k-quarter (16 k values)

    // ---- early LDG of chunk c0 ----
    float R[16];
#pragma unroll
    for (int i = 0; i < 16; ++i)
        R[i] = srcb[(size_t)(kg * 16 + i) * HW_ + (size_t)c0i * CHUNK_M + mcol];

    // ---- build A tile (208 rows; rows >= 200 zero-padded) ----
    if (tid < KP_PAD) {
        const int row = tid;
        const int kp = kphalf * KP_HALF + row;
        float v[CDIM];
        float ss = 0.f;
        if (row < KP_HALF) {
            const float* tb = kdesc + (size_t)tgt_ids[p] * CDIM * NKP + kp;
#pragma unroll
            for (int c = 0; c < CDIM; ++c) { v[c] = tb[c * NKP]; ss = fmaf(v[c], v[c], ss); }
        } else {
#pragma unroll
            for (int c = 0; c < CDIM; ++c) v[c] = 0.f;
            ss = 1.f;
        }
        float inv = LOGIT_C / fmaxf(sqrtf(ss), 1e-12f);
#pragma unroll
        for (int kb = 0; kb < CDIM; kb += 8) {
            uint32_t q[4];
#pragma unroll
            for (int j = 0; j < 4; ++j)
                q[j] = pkh2(v[kb + 2 * j] * inv, v[kb + 2 * j + 1] * inv);
            *(uint4*)(sm + SA + row * 144 + kb * 2) = make_uint4(q[0], q[1], q[2], q[3]);
        }
    }

    // ---- prologue: convert chunk c0 (norm via shfl), prefetch c0+1 ----
    {
        float ss = 0.f;
#pragma unroll
        for (int i = 0; i < 16; ++i) ss = fmaf(R[i], R[i], ss);
        ss += __shfl_xor_sync(0xffffffffu, ss, 8);
        ss += __shfl_xor_sync(0xffffffffu, ss, 16);
        float inv = 1.0f / fmaxf(sqrtf(ss), 1e-12f);
        char* bb = sm + SB + (c0i & 1) * 9216;
        uint32_t q[8];
#pragma unroll
        for (int j = 0; j < 8; ++j) q[j] = pkh2(R[2 * j] * inv, R[2 * j + 1] * inv);
        *(uint4*)(bb + mcol * 144 + kg * 32)      = make_uint4(q[0], q[1], q[2], q[3]);
        *(uint4*)(bb + mcol * 144 + kg * 32 + 16) = make_uint4(q[4], q[5], q[6], q[7]);
        if (c0i + 1 < c1i) {
#pragma unroll
            for (int i = 0; i < 16; ++i)
                R[i] = srcb[(size_t)(kg * 16 + i) * HW_ + (size_t)(c0i + 1) * CHUNK_M + mcol];
        }
    }

    // frag assignment: slot 0 = frag w; slot 1 = frag w+8 (warps 0-4 only)
    const int f1 = (w < 5) ? (w + 8) : -1;

    float S[2][2]  = {{0.f,0.f},{0.f,0.f}};
    float XO[2][2] = {{0.f,0.f},{0.f,0.f}};
    float XB[2][2] = {{0.f,0.f},{0.f,0.f}};
    float Yc[2][2] = {{0.f,0.f},{0.f,0.f}};

    const int preA = ((lane & 7) + ((lane >> 3) & 1) * 8) * 144 + ((lane >> 4) & 1) * 16;
    const int preB = ((lane & 7) + ((lane >> 4) & 1) * 8) * 144 + ((lane >> 3) & 1) * 16;
    const float xol = (float)((lane & 3) * 2);

    for (int t = c0i; t < c1i; ++t) {
        __syncthreads();   // buf[t&1] ready; prior chunk's readers of buf[(t+1)&1] done

        // ---- staging first: convert chunk t+1 into buf[(t+1)&1], prefetch t+2 ----
        if (t + 1 < c1i) {
            float ss = 0.f;
#pragma unroll
            for (int i = 0; i < 16; ++i) ss = fmaf(R[i], R[i], ss);
            ss += __shfl_xor_sync(0xffffffffu, ss, 8);
            ss += __shfl_xor_sync(0xffffffffu, ss, 16);
            float inv = 1.0f / fmaxf(sqrtf(ss), 1e-12f);
            char* bb = sm + SB + ((t + 1) & 1) * 9216;
            uint32_t q[8];
#pragma unroll
            for (int j = 0; j < 8; ++j) q[j] = pkh2(R[2 * j] * inv, R[2 * j + 1] * inv);
            *(uint4*)(bb + mcol * 144 + kg * 32)      = make_uint4(q[0], q[1], q[2], q[3]);
            *(uint4*)(bb + mcol * 144 + kg * 32 + 16) = make_uint4(q[4], q[5], q[6], q[7]);
            if (t + 2 < c1i) {
#pragma unroll
                for (int i = 0; i < 16; ++i)
                    R[i] = srcb[(size_t)(kg * 16 + i) * HW_ + (size_t)(t + 2) * CHUNK_M + mcol];
            }
        }

        // ---- compute chunk t (slots sequential, c[] reused -> low register count) ----
        const uint32_t Bb = sb + SB + (t & 1) * 9216;
        const int m0 = t * CHUNK_M;
        const float xb = (float)(m0 & 255), yv = (float)(m0 >> 8);

#pragma unroll
        for (int slot = 0; slot < 2; ++slot) {
            const int f = (slot == 0) ? w : f1;
            if (f < 0) continue;
            const uint32_t Ah = sb + SA + f * 16 * 144 + preA;
            float c[8][4];
#pragma unroll
            for (int ff = 0; ff < 8; ++ff)      // fold -100*log2e into accumulator init
                c[ff][0] = c[ff][1] = c[ff][2] = c[ff][3] = -LOGIT_C;

#pragma unroll
            for (int ks = 0; ks < 4; ++ks) {
                uint32_t ah[4];
                ldsm4(ah[0], ah[1], ah[2], ah[3], Ah + ks * 32);
#pragma unroll
                for (int fp = 0; fp < 4; ++fp) {
                    uint32_t b0, b1, b2, b3;
                    ldsm4(b0, b1, b2, b3, Bb + fp * 2304 + preB + ks * 32);
                    mma16816(c[2 * fp],     ah, b0, b1);
                    mma16816(c[2 * fp + 1], ah, b2, b3);
                }
            }

            // ---- epilogue: w = 2^c; rows = keypoints (in-register moments) ----
            float s0 = S[slot][0], s1 = S[slot][1];
            float x0 = XO[slot][0], x1 = XO[slot][1];
            const float sn0 = s0, sn1 = s1;
#pragma unroll
            for (int ff = 0; ff < 8; ++ff) {
                float xo = xol + (float)(ff * 8);
                float w0 = ex2f(c[ff][0]);
                float w1 = ex2f(c[ff][1]);
                float w2 = ex2f(c[ff][2]);
                float w3 = ex2f(c[ff][3]);
                s0 += w0 + w1;
                x0 = fmaf(w0, xo, x0); x0 = fmaf(w1, xo + 1.f, x0);
                s1 += w2 + w3;
                x1 = fmaf(w2, xo, x1); x1 = fmaf(w3, xo + 1.f, x1);
            }
            S[slot][0] = s0; S[slot][1] = s1; XO[slot][0] = x0; XO[slot][1] = x1;
            XB[slot][0] = fmaf(xb, s0 - sn0, XB[slot][0]);
            XB[slot][1] = fmaf(xb, s1 - sn1, XB[slot][1]);
            Yc[slot][0] = fmaf(yv, s0 - sn0, Yc[slot][0]);
            Yc[slot][1] = fmaf(yv, s1 - sn1, Yc[slot][1]);
        }
    }

    // ---- reduce over the 4 col-lanes and store partials (skip padding rows) ----
#pragma unroll
    for (int slot = 0; slot < 2; ++slot) {
        const int f = (slot == 0) ? w : f1;
        if (f < 0) continue;
#pragma unroll
        for (int rp = 0; rp < 2; ++rp) {
            float s = S[slot][rp], x = XO[slot][rp] + XB[slot][rp], y = Yc[slot][rp];
            s += __shfl_xor_sync(0xffffffffu, s, 1);
            x += __shfl_xor_sync(0xffffffffu, x, 1);
            y += __shfl_xor_sync(0xffffffffu, y, 1);
            s += __shfl_xor_sync(0xffffffffu, s, 2);
            x += __shfl_xor_sync(0xffffffffu, x, 2);
            y += __shfl_xor_sync(0xffffffffu, y, 2);
            if ((lane & 3) == 0) {
                int kpl = f * 16 + (lane >> 2) + 8 * rp;
                if (kpl < KP_HALF) {
                    int kp = kphalf * KP_HALF + kpl;
                    g_part4[((size_t)p * NKP + kp) * NSTRIP + strip] = make_float4(s, x, y, 0.f);
                }
            }
        }
    }
}

// ---------------- kernel 2: combine partials + emit scores/ids (4 kp / 128-thr block) ----------------
__global__ void k_combine(const float* __restrict__ kscores,
                          const int* __restrict__ tgt_ids, const int* __restrict__ src_ids,
                          float* __restrict__ out, int P, int out_size) {
    int gw   = blockIdx.x * 4 + (threadIdx.x >> 5);
    int lane = threadIdx.x & 31;
    if (blockIdx.x == 0 && threadIdx.x == 0) {
        int base = P * NKP * 3;
        for (int pp = 0; pp < P; ++pp) {
            if (base + pp < out_size)     out[base + pp]     = (float)tgt_ids[pp];
            if (base + P + pp < out_size) out[base + P + pp] = (float)src_ids[pp];
        }
    }
    if (gw >= P * NKP) return;
    int p = gw / NKP, kp = gw - p * NKP;
    const float4* base = &g_part4[((size_t)p * NKP + kp) * NSTRIP];
    float4 v0 = base[lane];
    float4 v1 = base[lane + 32];
    float4 v2 = (lane + 64 < NSTRIP) ? base[lane + 64] : make_float4(0.f, 0.f, 0.f, 0.f);
    float S = v0.x + v1.x + v2.x;
    float X = v0.y + v1.y + v2.y;
    float Y = v0.z + v1.z + v2.z;
#pragma unroll
    for (int off = 16; off; off >>= 1) {
        S += __shfl_xor_sync(0xffffffffu, S, off);
        X += __shfl_xor_sync(0xffffffffu, X, off);
        Y += __shfl_xor_sync(0xffffffffu, Y, off);
    }
    if (lane == 0) {
        if (gw * 2 + 1 < out_size) {
            out[gw * 2 + 0] = X / S;
            out[gw * 2 + 1] = Y / S;
        }
        int so = P * NKP * 2 + p * NKP + kp;
        if (so < out_size) out[so] = kscores[tgt_ids[p] * NKP + kp];
    }
}

// ---------------- launch ----------------
extern "C" void kernel_launch(void* const* d_in, const int* in_sizes, int n_in,
                              void* d_out, int out_size) {
    const float* kscores = (const float*)d_in[0];
    const float* kdesc   = (const float*)d_in[1];
    const float* dense   = (const float*)d_in[2];
    const int*   tgt_ids = (const int*)d_in[3];
    const int*   src_ids = (const int*)d_in[4];
    int P = in_sizes[3];
    if (P > PMAX) P = PMAX;
    float* out = (float*)d_out;

    cudaFuncSetAttribute(k_match, cudaFuncAttributeMaxDynamicSharedMemorySize, SMEMSZ);
    k_match<<<dim3(NSTRIP, 2, P), NTHREADS, SMEMSZ>>>(dense, kdesc, tgt_ids, src_ids);

    k_combine<<<(P * NKP + 3) / 4, 128>>>(kscores, tgt_ids, src_ids, out, P, out_size);
}